// round 3
// baseline (speedup 1.0000x reference)
#include <cuda_runtime.h>
#include <cstdint>

// ---------------- Problem constants ----------------
#define N_TOK   4096          // H*W = 64*64
#define C_DIM   256
#define HQKV    512           // DIM + 2*KEY_DIM*NUM_HEADS
#define NH      8
#define KD      16            // KEY_DIM
#define HD      32            // HEAD_DIM
#define SCALE_F 0.25f         // KEY_DIM^-0.5
#define EPS_F   1e-3f
#define BATCH   2

// ---------------- Scratch (device globals: no allocations allowed) --------
__device__ float g_qkv[BATCH * HQKV * N_TOK];   // 16 MB  [b][o][n], o in qkv order
__device__ float g_att[BATCH * C_DIM * N_TOK];  //  8 MB  [b][h*32+d][n]
__device__ float g_pe [BATCH * C_DIM * N_TOK];  //  8 MB  [b][c][n]

// ===========================================================================
// GEMM + fused BN.
//   MODE 0: qkv   : Out = g_qkv,  X = param x        (M = 512)
//   MODE 1: proj  : Out = param,  X = g_att + g_pe   (M = 256)
// Out[b][o][n] = (sum_c A[o][c] * X[b][c][n]) * s[o] + t[o]
// 64x64 tile, BK=16, 256 threads, 4x4 micro-tile.
// ===========================================================================
template <int MODE>
__global__ __launch_bounds__(256)
void gemm_bn_kernel(const float* __restrict__ A,
                    const float* __restrict__ Xp,
                    float* __restrict__ Outp,
                    const float* __restrict__ bn_g,
                    const float* __restrict__ bn_b,
                    const float* __restrict__ bn_m,
                    const float* __restrict__ bn_v)
{
    constexpr int M = (MODE == 0) ? HQKV : C_DIM;

    __shared__ __align__(16) float As[16][64];
    __shared__ __align__(16) float Bs[16][64];

    const int bz = blockIdx.z;
    const int n0 = blockIdx.x * 64;
    const int m0 = blockIdx.y * 64;
    const int t  = threadIdx.x;
    const int tx = t & 15;       // 0..15 -> n
    const int ty = t >> 4;       // 0..15 -> m

    const float* __restrict__ Xb;
    const float* __restrict__ X2b = nullptr;
    float* __restrict__ Ob;
    if (MODE == 0) {
        Xb = Xp + (size_t)bz * C_DIM * N_TOK;
        Ob = g_qkv + (size_t)bz * HQKV * N_TOK;
    } else {
        Xb  = g_att + (size_t)bz * C_DIM * N_TOK;
        X2b = g_pe  + (size_t)bz * C_DIM * N_TOK;
        Ob  = Outp + (size_t)bz * C_DIM * N_TOK;
    }

    float acc[4][4];
#pragma unroll
    for (int i = 0; i < 4; i++)
#pragma unroll
        for (int j = 0; j < 4; j++) acc[i][j] = 0.f;

    const int arow = t >> 2;            // 0..63
    const int acq  = (t & 3) * 4;       // 0,4,8,12
    const int bk   = t >> 4;            // 0..15
    const int bj   = (t & 15) * 4;      // 0..60

    for (int k0 = 0; k0 < C_DIM; k0 += 16) {
        __syncthreads();
        // A tile: 64 rows x 16 k, transposed store
        {
            float4 av = *(const float4*)&A[(size_t)(m0 + arow) * C_DIM + k0 + acq];
            As[acq + 0][arow] = av.x;
            As[acq + 1][arow] = av.y;
            As[acq + 2][arow] = av.z;
            As[acq + 3][arow] = av.w;
        }
        // B tile: 16 k-rows x 64 n (fused residual add for proj)
        {
            float4 xv = *(const float4*)&Xb[(size_t)(k0 + bk) * N_TOK + n0 + bj];
            if (MODE == 1) {
                float4 pv = *(const float4*)&X2b[(size_t)(k0 + bk) * N_TOK + n0 + bj];
                xv.x += pv.x; xv.y += pv.y; xv.z += pv.z; xv.w += pv.w;
            }
            *(float4*)&Bs[bk][bj] = xv;
        }
        __syncthreads();
#pragma unroll
        for (int kk = 0; kk < 16; kk++) {
            float a[4], bq[4];
            *(float4*)a  = *(const float4*)&As[kk][ty * 4];
            *(float4*)bq = *(const float4*)&Bs[kk][tx * 4];
#pragma unroll
            for (int i = 0; i < 4; i++)
#pragma unroll
                for (int j = 0; j < 4; j++)
                    acc[i][j] += a[i] * bq[j];
        }
    }

#pragma unroll
    for (int i = 0; i < 4; i++) {
        const int o = m0 + ty * 4 + i;
        const float s  = bn_g[o] * rsqrtf(bn_v[o] + EPS_F);
        const float sh = bn_b[o] - bn_m[o] * s;
        float4 r;
        r.x = acc[i][0] * s + sh;
        r.y = acc[i][1] * s + sh;
        r.z = acc[i][2] * s + sh;
        r.w = acc[i][3] * s + sh;
        *(float4*)&Ob[(size_t)o * N_TOK + n0 + tx * 4] = r;
    }
}

// ===========================================================================
// Depthwise 3x3 conv on V (v_img channel c -> qkv row (c>>5)*64 + 32 + (c&31))
// + fused BN -> g_pe[b][c][n]
// ===========================================================================
__global__ __launch_bounds__(256)
void dwconv_bn_kernel(const float* __restrict__ w_pe,
                      const float* __restrict__ bn_g,
                      const float* __restrict__ bn_b,
                      const float* __restrict__ bn_m,
                      const float* __restrict__ bn_v)
{
    const int idx = blockIdx.x * 256 + threadIdx.x;   // pixel 0..4095
    const int bc  = blockIdx.y;                       // 0..511
    const int b = bc >> 8, c = bc & 255;
    const float* __restrict__ src =
        g_qkv + (size_t)(b * HQKV + (c >> 5) * 64 + 32 + (c & 31)) * N_TOK;
    const int hh = idx >> 6, ww = idx & 63;
    const float* __restrict__ wp = w_pe + c * 9;

    float acc = 0.f;
#pragma unroll
    for (int dy = -1; dy <= 1; dy++) {
        const int y = hh + dy;
        if ((unsigned)y < 64u) {
#pragma unroll
            for (int dx = -1; dx <= 1; dx++) {
                const int x = ww + dx;
                if ((unsigned)x < 64u)
                    acc += wp[(dy + 1) * 3 + (dx + 1)] * src[y * 64 + x];
            }
        }
    }
    const float s  = bn_g[c] * rsqrtf(bn_v[c] + EPS_F);
    const float sh = bn_b[c] - bn_m[c] * s;
    g_pe[(size_t)bc * N_TOK + idx] = acc * s + sh;
}

// ===========================================================================
// Flash-style attention, single-pass online softmax (no running max; scores
// are O(1) in magnitude here, exp() cannot overflow fp32).
// CTA: one (b,h), 256 query tokens; 128 threads x 2 queries each.
// K/V chunks (128 keys) staged in smem TRANSPOSED with padded strides
// (20 / 36 floats) -> per-key column = 4+8 broadcast LDS.128.
// ===========================================================================
__global__ __launch_bounds__(128)
void attn_kernel()
{
    __shared__ __align__(16) float ks[128 * 20];   // [m][16 k-dims], stride 20
    __shared__ __align__(16) float vs[128 * 36];   // [m][32 v-dims], stride 36

    const int t  = threadIdx.x;                    // 0..127
    const int bh = blockIdx.y;                     // 0..15
    const int b = bh >> 3, h = bh & 7;
    const int n0 = blockIdx.x * 256;

    const float* __restrict__ qb = g_qkv + (size_t)(b * HQKV + h * 64) * N_TOK;
    const float* __restrict__ kb = qb + (size_t)KD * N_TOK;
    const float* __restrict__ vb = qb + (size_t)(2 * KD) * N_TOK;

    // Two query columns per thread, pre-scaled by SCALE.
    float q0[16], q1[16];
#pragma unroll
    for (int j = 0; j < 16; j++) {
        q0[j] = qb[(size_t)j * N_TOK + n0 + t]       * SCALE_F;
        q1[j] = qb[(size_t)j * N_TOK + n0 + 128 + t] * SCALE_F;
    }

    float acc0[32], acc1[32];
#pragma unroll
    for (int d = 0; d < 32; d++) { acc0[d] = 0.f; acc1[d] = 0.f; }
    float l0 = 0.f, l1 = 0.f;

    for (int m0 = 0; m0 < N_TOK; m0 += 128) {
        __syncthreads();
        // Thread t owns key column m = t: coalesced global reads,
        // transposed smem writes (4-way STS conflicts, load phase only).
#pragma unroll
        for (int j = 0; j < 16; j++)
            ks[t * 20 + j] = kb[(size_t)j * N_TOK + m0 + t];
#pragma unroll
        for (int d = 0; d < 32; d++)
            vs[t * 36 + d] = vb[(size_t)d * N_TOK + m0 + t];
        __syncthreads();

#pragma unroll 4
        for (int m = 0; m < 128; m++) {
            const float4* kc = (const float4*)(ks + m * 20);
            float s0 = 0.f, s1 = 0.f;
#pragma unroll
            for (int jq = 0; jq < 4; jq++) {
                const float4 kk4 = kc[jq];
                s0 += q0[jq * 4 + 0] * kk4.x + q0[jq * 4 + 1] * kk4.y
                    + q0[jq * 4 + 2] * kk4.z + q0[jq * 4 + 3] * kk4.w;
                s1 += q1[jq * 4 + 0] * kk4.x + q1[jq * 4 + 1] * kk4.y
                    + q1[jq * 4 + 2] * kk4.z + q1[jq * 4 + 3] * kk4.w;
            }
            const float p0 = __expf(s0);
            const float p1 = __expf(s1);
            l0 += p0; l1 += p1;
            const float4* vc = (const float4*)(vs + m * 36);
#pragma unroll
            for (int dq = 0; dq < 8; dq++) {
                const float4 vv = vc[dq];
                acc0[dq * 4 + 0] += p0 * vv.x; acc0[dq * 4 + 1] += p0 * vv.y;
                acc0[dq * 4 + 2] += p0 * vv.z; acc0[dq * 4 + 3] += p0 * vv.w;
                acc1[dq * 4 + 0] += p1 * vv.x; acc1[dq * 4 + 1] += p1 * vv.y;
                acc1[dq * 4 + 2] += p1 * vv.z; acc1[dq * 4 + 3] += p1 * vv.w;
            }
        }
    }

    const float r0 = 1.f / l0;
    const float r1 = 1.f / l1;
    float* __restrict__ ob = g_att + (size_t)(b * C_DIM + h * HD) * N_TOK + n0 + t;
#pragma unroll
    for (int d = 0; d < 32; d++) {
        ob[(size_t)d * N_TOK]       = acc0[d] * r0;
        ob[(size_t)d * N_TOK + 128] = acc1[d] * r1;
    }
}

// ===========================================================================
// Launch
// ===========================================================================
extern "C" void kernel_launch(void* const* d_in, const int* in_sizes, int n_in,
                              void* d_out, int out_size)
{
    const float* x       = (const float*)d_in[0];
    const float* w_qkv   = (const float*)d_in[1];
    const float* qkv_g   = (const float*)d_in[2];
    const float* qkv_b   = (const float*)d_in[3];
    const float* qkv_m   = (const float*)d_in[4];
    const float* qkv_v   = (const float*)d_in[5];
    const float* w_pe    = (const float*)d_in[6];
    const float* pe_g    = (const float*)d_in[7];
    const float* pe_b    = (const float*)d_in[8];
    const float* pe_m    = (const float*)d_in[9];
    const float* pe_v    = (const float*)d_in[10];
    const float* w_proj  = (const float*)d_in[11];
    const float* proj_g  = (const float*)d_in[12];
    const float* proj_b  = (const float*)d_in[13];
    const float* proj_m  = (const float*)d_in[14];
    const float* proj_v  = (const float*)d_in[15];
    float* out = (float*)d_out;

    // 1) qkv GEMM + BN -> g_qkv
    {
        dim3 grid(N_TOK / 64, HQKV / 64, BATCH);
        gemm_bn_kernel<0><<<grid, 256>>>(w_qkv, x, nullptr,
                                         qkv_g, qkv_b, qkv_m, qkv_v);
    }
    // 2) depthwise 3x3 PE conv + BN -> g_pe
    {
        dim3 grid(N_TOK / 256, BATCH * C_DIM);
        dwconv_bn_kernel<<<grid, 256>>>(w_pe, pe_g, pe_b, pe_m, pe_v);
    }
    // 3) attention -> g_att
    {
        dim3 grid(N_TOK / 256, BATCH * NH);
        attn_kernel<<<grid, 128>>>();
    }
    // 4) proj GEMM on (g_att + g_pe) + BN -> out
    {
        dim3 grid(N_TOK / 64, C_DIM / 64, BATCH);
        gemm_bn_kernel<1><<<grid, 256>>>(w_proj, nullptr, out,
                                         proj_g, proj_b, proj_m, proj_v);
    }
    (void)in_sizes; (void)n_in; (void)out_size;
}

// round 4
// speedup vs baseline: 1.0003x; 1.0003x over previous
#include <cuda_runtime.h>
#include <cstdint>

// ---------------- Problem constants ----------------
#define N_TOK   4096          // H*W = 64*64
#define C_DIM   256
#define HQKV    512           // DIM + 2*KEY_DIM*NUM_HEADS
#define NH      8
#define KD      16            // KEY_DIM
#define HD      32            // HEAD_DIM
#define SCALE_F 0.25f         // KEY_DIM^-0.5
#define EPS_F   1e-3f
#define BATCH   2

// ---------------- Scratch (device globals: no allocations allowed) --------
__device__ float g_qkv[BATCH * HQKV * N_TOK];   // 16 MB  [b][o][n], o in qkv order
__device__ float g_att[BATCH * C_DIM * N_TOK];  //  8 MB  [b][h*32+d][n]
__device__ float g_pe [BATCH * C_DIM * N_TOK];  //  8 MB  [b][c][n]

// ===========================================================================
// GEMM + fused BN.
//   MODE 0: qkv   : Out = g_qkv,  X = param x        (M = 512)
//   MODE 1: proj  : Out = param,  X = g_att + g_pe   (M = 256)
// Out[b][o][n] = (sum_c A[o][c] * X[b][c][n]) * s[o] + t[o]
// 64x64 tile, BK=16, 256 threads, 4x4 micro-tile.
// ===========================================================================
template <int MODE>
__global__ __launch_bounds__(256)
void gemm_bn_kernel(const float* __restrict__ A,
                    const float* __restrict__ Xp,
                    float* __restrict__ Outp,
                    const float* __restrict__ bn_g,
                    const float* __restrict__ bn_b,
                    const float* __restrict__ bn_m,
                    const float* __restrict__ bn_v)
{
    constexpr int M = (MODE == 0) ? HQKV : C_DIM;

    __shared__ __align__(16) float As[16][64];
    __shared__ __align__(16) float Bs[16][64];

    const int bz = blockIdx.z;
    const int n0 = blockIdx.x * 64;
    const int m0 = blockIdx.y * 64;
    const int t  = threadIdx.x;
    const int tx = t & 15;       // 0..15 -> n
    const int ty = t >> 4;       // 0..15 -> m

    const float* __restrict__ Xb;
    const float* __restrict__ X2b = nullptr;
    float* __restrict__ Ob;
    if (MODE == 0) {
        Xb = Xp + (size_t)bz * C_DIM * N_TOK;
        Ob = g_qkv + (size_t)bz * HQKV * N_TOK;
    } else {
        Xb  = g_att + (size_t)bz * C_DIM * N_TOK;
        X2b = g_pe  + (size_t)bz * C_DIM * N_TOK;
        Ob  = Outp + (size_t)bz * C_DIM * N_TOK;
    }

    float acc[4][4];
#pragma unroll
    for (int i = 0; i < 4; i++)
#pragma unroll
        for (int j = 0; j < 4; j++) acc[i][j] = 0.f;

    const int arow = t >> 2;            // 0..63
    const int acq  = (t & 3) * 4;       // 0,4,8,12
    const int bk   = t >> 4;            // 0..15
    const int bj   = (t & 15) * 4;      // 0..60

    for (int k0 = 0; k0 < C_DIM; k0 += 16) {
        __syncthreads();
        // A tile: 64 rows x 16 k, transposed store
        {
            float4 av = *(const float4*)&A[(size_t)(m0 + arow) * C_DIM + k0 + acq];
            As[acq + 0][arow] = av.x;
            As[acq + 1][arow] = av.y;
            As[acq + 2][arow] = av.z;
            As[acq + 3][arow] = av.w;
        }
        // B tile: 16 k-rows x 64 n (fused residual add for proj)
        {
            float4 xv = *(const float4*)&Xb[(size_t)(k0 + bk) * N_TOK + n0 + bj];
            if (MODE == 1) {
                float4 pv = *(const float4*)&X2b[(size_t)(k0 + bk) * N_TOK + n0 + bj];
                xv.x += pv.x; xv.y += pv.y; xv.z += pv.z; xv.w += pv.w;
            }
            *(float4*)&Bs[bk][bj] = xv;
        }
        __syncthreads();
#pragma unroll
        for (int kk = 0; kk < 16; kk++) {
            float a[4], bq[4];
            *(float4*)a  = *(const float4*)&As[kk][ty * 4];
            *(float4*)bq = *(const float4*)&Bs[kk][tx * 4];
#pragma unroll
            for (int i = 0; i < 4; i++)
#pragma unroll
                for (int j = 0; j < 4; j++)
                    acc[i][j] += a[i] * bq[j];
        }
    }

#pragma unroll
    for (int i = 0; i < 4; i++) {
        const int o = m0 + ty * 4 + i;
        const float s  = bn_g[o] * rsqrtf(bn_v[o] + EPS_F);
        const float sh = bn_b[o] - bn_m[o] * s;
        float4 r;
        r.x = acc[i][0] * s + sh;
        r.y = acc[i][1] * s + sh;
        r.z = acc[i][2] * s + sh;
        r.w = acc[i][3] * s + sh;
        *(float4*)&Ob[(size_t)o * N_TOK + n0 + tx * 4] = r;
    }
}

// ===========================================================================
// Depthwise 3x3 conv on V (v_img channel c -> qkv row (c>>5)*64 + 32 + (c&31))
// + fused BN -> g_pe[b][c][n]
// ===========================================================================
__global__ __launch_bounds__(256)
void dwconv_bn_kernel(const float* __restrict__ w_pe,
                      const float* __restrict__ bn_g,
                      const float* __restrict__ bn_b,
                      const float* __restrict__ bn_m,
                      const float* __restrict__ bn_v)
{
    const int idx = blockIdx.x * 256 + threadIdx.x;   // pixel 0..4095
    const int bc  = blockIdx.y;                       // 0..511
    const int b = bc >> 8, c = bc & 255;
    const float* __restrict__ src =
        g_qkv + (size_t)(b * HQKV + (c >> 5) * 64 + 32 + (c & 31)) * N_TOK;
    const int hh = idx >> 6, ww = idx & 63;
    const float* __restrict__ wp = w_pe + c * 9;

    float acc = 0.f;
#pragma unroll
    for (int dy = -1; dy <= 1; dy++) {
        const int y = hh + dy;
        if ((unsigned)y < 64u) {
#pragma unroll
            for (int dx = -1; dx <= 1; dx++) {
                const int x = ww + dx;
                if ((unsigned)x < 64u)
                    acc += wp[(dy + 1) * 3 + (dx + 1)] * src[y * 64 + x];
            }
        }
    }
    const float s  = bn_g[c] * rsqrtf(bn_v[c] + EPS_F);
    const float sh = bn_b[c] - bn_m[c] * s;
    g_pe[(size_t)bc * N_TOK + idx] = acc * s + sh;
}

// ===========================================================================
// Flash-style attention, single-pass online softmax (no running max; scores
// are O(1) in magnitude here, exp() cannot overflow fp32).
// CTA: one (b,h), 256 query tokens; 128 threads x 2 queries each.
// K/V chunks (128 keys) staged in smem TRANSPOSED with padded strides
// (20 / 36 floats) -> per-key column = 4+8 broadcast LDS.128.
// ===========================================================================
__global__ __launch_bounds__(128)
void attn_kernel()
{
    __shared__ __align__(16) float ks[128 * 20];   // [m][16 k-dims], stride 20
    __shared__ __align__(16) float vs[128 * 36];   // [m][32 v-dims], stride 36

    const int t  = threadIdx.x;                    // 0..127
    const int bh = blockIdx.y;                     // 0..15
    const int b = bh >> 3, h = bh & 7;
    const int n0 = blockIdx.x * 256;

    const float* __restrict__ qb = g_qkv + (size_t)(b * HQKV + h * 64) * N_TOK;
    const float* __restrict__ kb = qb + (size_t)KD * N_TOK;
    const float* __restrict__ vb = qb + (size_t)(2 * KD) * N_TOK;

    // Two query columns per thread, pre-scaled by SCALE.
    float q0[16], q1[16];
#pragma unroll
    for (int j = 0; j < 16; j++) {
        q0[j] = qb[(size_t)j * N_TOK + n0 + t]       * SCALE_F;
        q1[j] = qb[(size_t)j * N_TOK + n0 + 128 + t] * SCALE_F;
    }

    float acc0[32], acc1[32];
#pragma unroll
    for (int d = 0; d < 32; d++) { acc0[d] = 0.f; acc1[d] = 0.f; }
    float l0 = 0.f, l1 = 0.f;

    for (int m0 = 0; m0 < N_TOK; m0 += 128) {
        __syncthreads();
        // Thread t owns key column m = t: coalesced global reads,
        // transposed smem writes (4-way STS conflicts, load phase only).
#pragma unroll
        for (int j = 0; j < 16; j++)
            ks[t * 20 + j] = kb[(size_t)j * N_TOK + m0 + t];
#pragma unroll
        for (int d = 0; d < 32; d++)
            vs[t * 36 + d] = vb[(size_t)d * N_TOK + m0 + t];
        __syncthreads();

#pragma unroll 4
        for (int m = 0; m < 128; m++) {
            const float4* kc = (const float4*)(ks + m * 20);
            float s0 = 0.f, s1 = 0.f;
#pragma unroll
            for (int jq = 0; jq < 4; jq++) {
                const float4 kk4 = kc[jq];
                s0 += q0[jq * 4 + 0] * kk4.x + q0[jq * 4 + 1] * kk4.y
                    + q0[jq * 4 + 2] * kk4.z + q0[jq * 4 + 3] * kk4.w;
                s1 += q1[jq * 4 + 0] * kk4.x + q1[jq * 4 + 1] * kk4.y
                    + q1[jq * 4 + 2] * kk4.z + q1[jq * 4 + 3] * kk4.w;
            }
            const float p0 = __expf(s0);
            const float p1 = __expf(s1);
            l0 += p0; l1 += p1;
            const float4* vc = (const float4*)(vs + m * 36);
#pragma unroll
            for (int dq = 0; dq < 8; dq++) {
                const float4 vv = vc[dq];
                acc0[dq * 4 + 0] += p0 * vv.x; acc0[dq * 4 + 1] += p0 * vv.y;
                acc0[dq * 4 + 2] += p0 * vv.z; acc0[dq * 4 + 3] += p0 * vv.w;
                acc1[dq * 4 + 0] += p1 * vv.x; acc1[dq * 4 + 1] += p1 * vv.y;
                acc1[dq * 4 + 2] += p1 * vv.z; acc1[dq * 4 + 3] += p1 * vv.w;
            }
        }
    }

    const float r0 = 1.f / l0;
    const float r1 = 1.f / l1;
    float* __restrict__ ob = g_att + (size_t)(b * C_DIM + h * HD) * N_TOK + n0 + t;
#pragma unroll
    for (int d = 0; d < 32; d++) {
        ob[(size_t)d * N_TOK]       = acc0[d] * r0;
        ob[(size_t)d * N_TOK + 128] = acc1[d] * r1;
    }
}

// ===========================================================================
// Launch
// ===========================================================================
extern "C" void kernel_launch(void* const* d_in, const int* in_sizes, int n_in,
                              void* d_out, int out_size)
{
    const float* x       = (const float*)d_in[0];
    const float* w_qkv   = (const float*)d_in[1];
    const float* qkv_g   = (const float*)d_in[2];
    const float* qkv_b   = (const float*)d_in[3];
    const float* qkv_m   = (const float*)d_in[4];
    const float* qkv_v   = (const float*)d_in[5];
    const float* w_pe    = (const float*)d_in[6];
    const float* pe_g    = (const float*)d_in[7];
    const float* pe_b    = (const float*)d_in[8];
    const float* pe_m    = (const float*)d_in[9];
    const float* pe_v    = (const float*)d_in[10];
    const float* w_proj  = (const float*)d_in[11];
    const float* proj_g  = (const float*)d_in[12];
    const float* proj_b  = (const float*)d_in[13];
    const float* proj_m  = (const float*)d_in[14];
    const float* proj_v  = (const float*)d_in[15];
    float* out = (float*)d_out;

    // 1) qkv GEMM + BN -> g_qkv
    {
        dim3 grid(N_TOK / 64, HQKV / 64, BATCH);
        gemm_bn_kernel<0><<<grid, 256>>>(w_qkv, x, nullptr,
                                         qkv_g, qkv_b, qkv_m, qkv_v);
    }
    // 2) depthwise 3x3 PE conv + BN -> g_pe
    {
        dim3 grid(N_TOK / 256, BATCH * C_DIM);
        dwconv_bn_kernel<<<grid, 256>>>(w_pe, pe_g, pe_b, pe_m, pe_v);
    }
    // 3) attention -> g_att
    {
        dim3 grid(N_TOK / 256, BATCH * NH);
        attn_kernel<<<grid, 128>>>();
    }
    // 4) proj GEMM on (g_att + g_pe) + BN -> out
    {
        dim3 grid(N_TOK / 64, C_DIM / 64, BATCH);
        gemm_bn_kernel<1><<<grid, 256>>>(w_proj, nullptr, out,
                                         proj_g, proj_b, proj_m, proj_v);
    }
    (void)in_sizes; (void)n_in; (void)out_size;
}

// round 5
// speedup vs baseline: 1.0007x; 1.0004x over previous
#include <cuda_runtime.h>
#include <cstdint>

// ---------------- Problem constants ----------------
#define N_TOK   4096          // H*W = 64*64
#define C_DIM   256
#define HQKV    512           // DIM + 2*KEY_DIM*NUM_HEADS
#define NH      8
#define KD      16            // KEY_DIM
#define HD      32            // HEAD_DIM
#define SCALE_F 0.25f         // KEY_DIM^-0.5
#define EPS_F   1e-3f
#define BATCH   2

// ---------------- Scratch (device globals: no allocations allowed) --------
__device__ float g_qkv[BATCH * HQKV * N_TOK];   // 16 MB  [b][o][n], o in qkv order
__device__ float g_att[BATCH * C_DIM * N_TOK];  //  8 MB  [b][h*32+d][n]
__device__ float g_pe [BATCH * C_DIM * N_TOK];  //  8 MB  [b][c][n]

// ===========================================================================
// GEMM + fused BN.
//   MODE 0: qkv   : Out = g_qkv,  X = param x        (M = 512)
//   MODE 1: proj  : Out = param,  X = g_att + g_pe   (M = 256)
// Out[b][o][n] = (sum_c A[o][c] * X[b][c][n]) * s[o] + t[o]
// 64x64 tile, BK=16, 256 threads, 4x4 micro-tile.
// ===========================================================================
template <int MODE>
__global__ __launch_bounds__(256)
void gemm_bn_kernel(const float* __restrict__ A,
                    const float* __restrict__ Xp,
                    float* __restrict__ Outp,
                    const float* __restrict__ bn_g,
                    const float* __restrict__ bn_b,
                    const float* __restrict__ bn_m,
                    const float* __restrict__ bn_v)
{
    constexpr int M = (MODE == 0) ? HQKV : C_DIM;

    __shared__ __align__(16) float As[16][64];
    __shared__ __align__(16) float Bs[16][64];

    const int bz = blockIdx.z;
    const int n0 = blockIdx.x * 64;
    const int m0 = blockIdx.y * 64;
    const int t  = threadIdx.x;
    const int tx = t & 15;       // 0..15 -> n
    const int ty = t >> 4;       // 0..15 -> m

    const float* __restrict__ Xb;
    const float* __restrict__ X2b = nullptr;
    float* __restrict__ Ob;
    if (MODE == 0) {
        Xb = Xp + (size_t)bz * C_DIM * N_TOK;
        Ob = g_qkv + (size_t)bz * HQKV * N_TOK;
    } else {
        Xb  = g_att + (size_t)bz * C_DIM * N_TOK;
        X2b = g_pe  + (size_t)bz * C_DIM * N_TOK;
        Ob  = Outp + (size_t)bz * C_DIM * N_TOK;
    }

    float acc[4][4];
#pragma unroll
    for (int i = 0; i < 4; i++)
#pragma unroll
        for (int j = 0; j < 4; j++) acc[i][j] = 0.f;

    const int arow = t >> 2;            // 0..63
    const int acq  = (t & 3) * 4;       // 0,4,8,12
    const int bk   = t >> 4;            // 0..15
    const int bj   = (t & 15) * 4;      // 0..60

    for (int k0 = 0; k0 < C_DIM; k0 += 16) {
        __syncthreads();
        // A tile: 64 rows x 16 k, transposed store
        {
            float4 av = *(const float4*)&A[(size_t)(m0 + arow) * C_DIM + k0 + acq];
            As[acq + 0][arow] = av.x;
            As[acq + 1][arow] = av.y;
            As[acq + 2][arow] = av.z;
            As[acq + 3][arow] = av.w;
        }
        // B tile: 16 k-rows x 64 n (fused residual add for proj)
        {
            float4 xv = *(const float4*)&Xb[(size_t)(k0 + bk) * N_TOK + n0 + bj];
            if (MODE == 1) {
                float4 pv = *(const float4*)&X2b[(size_t)(k0 + bk) * N_TOK + n0 + bj];
                xv.x += pv.x; xv.y += pv.y; xv.z += pv.z; xv.w += pv.w;
            }
            *(float4*)&Bs[bk][bj] = xv;
        }
        __syncthreads();
#pragma unroll
        for (int kk = 0; kk < 16; kk++) {
            float a[4], bq[4];
            *(float4*)a  = *(const float4*)&As[kk][ty * 4];
            *(float4*)bq = *(const float4*)&Bs[kk][tx * 4];
#pragma unroll
            for (int i = 0; i < 4; i++)
#pragma unroll
                for (int j = 0; j < 4; j++)
                    acc[i][j] += a[i] * bq[j];
        }
    }

#pragma unroll
    for (int i = 0; i < 4; i++) {
        const int o = m0 + ty * 4 + i;
        const float s  = bn_g[o] * rsqrtf(bn_v[o] + EPS_F);
        const float sh = bn_b[o] - bn_m[o] * s;
        float4 r;
        r.x = acc[i][0] * s + sh;
        r.y = acc[i][1] * s + sh;
        r.z = acc[i][2] * s + sh;
        r.w = acc[i][3] * s + sh;
        *(float4*)&Ob[(size_t)o * N_TOK + n0 + tx * 4] = r;
    }
}

// ===========================================================================
// Depthwise 3x3 conv on V (v_img channel c -> qkv row (c>>5)*64 + 32 + (c&31))
// + fused BN -> g_pe[b][c][n]
// ===========================================================================
__global__ __launch_bounds__(256)
void dwconv_bn_kernel(const float* __restrict__ w_pe,
                      const float* __restrict__ bn_g,
                      const float* __restrict__ bn_b,
                      const float* __restrict__ bn_m,
                      const float* __restrict__ bn_v)
{
    const int idx = blockIdx.x * 256 + threadIdx.x;   // pixel 0..4095
    const int bc  = blockIdx.y;                       // 0..511
    const int b = bc >> 8, c = bc & 255;
    const float* __restrict__ src =
        g_qkv + (size_t)(b * HQKV + (c >> 5) * 64 + 32 + (c & 31)) * N_TOK;
    const int hh = idx >> 6, ww = idx & 63;
    const float* __restrict__ wp = w_pe + c * 9;

    float acc = 0.f;
#pragma unroll
    for (int dy = -1; dy <= 1; dy++) {
        const int y = hh + dy;
        if ((unsigned)y < 64u) {
#pragma unroll
            for (int dx = -1; dx <= 1; dx++) {
                const int x = ww + dx;
                if ((unsigned)x < 64u)
                    acc += wp[(dy + 1) * 3 + (dx + 1)] * src[y * 64 + x];
            }
        }
    }
    const float s  = bn_g[c] * rsqrtf(bn_v[c] + EPS_F);
    const float sh = bn_b[c] - bn_m[c] * s;
    g_pe[(size_t)bc * N_TOK + idx] = acc * s + sh;
}

// ===========================================================================
// Flash-style attention, single-pass online softmax (no running max; scores
// are O(1) in magnitude here, exp() cannot overflow fp32).
// CTA: one (b,h), 256 query tokens; 128 threads x 2 queries each.
// K/V chunks (128 keys) staged in smem TRANSPOSED with padded strides
// (20 / 36 floats) -> per-key column = 4+8 broadcast LDS.128.
// ===========================================================================
__global__ __launch_bounds__(128)
void attn_kernel()
{
    __shared__ __align__(16) float ks[128 * 20];   // [m][16 k-dims], stride 20
    __shared__ __align__(16) float vs[128 * 36];   // [m][32 v-dims], stride 36

    const int t  = threadIdx.x;                    // 0..127
    const int bh = blockIdx.y;                     // 0..15
    const int b = bh >> 3, h = bh & 7;
    const int n0 = blockIdx.x * 256;

    const float* __restrict__ qb = g_qkv + (size_t)(b * HQKV + h * 64) * N_TOK;
    const float* __restrict__ kb = qb + (size_t)KD * N_TOK;
    const float* __restrict__ vb = qb + (size_t)(2 * KD) * N_TOK;

    // Two query columns per thread, pre-scaled by SCALE.
    float q0[16], q1[16];
#pragma unroll
    for (int j = 0; j < 16; j++) {
        q0[j] = qb[(size_t)j * N_TOK + n0 + t]       * SCALE_F;
        q1[j] = qb[(size_t)j * N_TOK + n0 + 128 + t] * SCALE_F;
    }

    float acc0[32], acc1[32];
#pragma unroll
    for (int d = 0; d < 32; d++) { acc0[d] = 0.f; acc1[d] = 0.f; }
    float l0 = 0.f, l1 = 0.f;

    for (int m0 = 0; m0 < N_TOK; m0 += 128) {
        __syncthreads();
        // Thread t owns key column m = t: coalesced global reads,
        // transposed smem writes (4-way STS conflicts, load phase only).
#pragma unroll
        for (int j = 0; j < 16; j++)
            ks[t * 20 + j] = kb[(size_t)j * N_TOK + m0 + t];
#pragma unroll
        for (int d = 0; d < 32; d++)
            vs[t * 36 + d] = vb[(size_t)d * N_TOK + m0 + t];
        __syncthreads();

#pragma unroll 4
        for (int m = 0; m < 128; m++) {
            const float4* kc = (const float4*)(ks + m * 20);
            float s0 = 0.f, s1 = 0.f;
#pragma unroll
            for (int jq = 0; jq < 4; jq++) {
                const float4 kk4 = kc[jq];
                s0 += q0[jq * 4 + 0] * kk4.x + q0[jq * 4 + 1] * kk4.y
                    + q0[jq * 4 + 2] * kk4.z + q0[jq * 4 + 3] * kk4.w;
                s1 += q1[jq * 4 + 0] * kk4.x + q1[jq * 4 + 1] * kk4.y
                    + q1[jq * 4 + 2] * kk4.z + q1[jq * 4 + 3] * kk4.w;
            }
            const float p0 = __expf(s0);
            const float p1 = __expf(s1);
            l0 += p0; l1 += p1;
            const float4* vc = (const float4*)(vs + m * 36);
#pragma unroll
            for (int dq = 0; dq < 8; dq++) {
                const float4 vv = vc[dq];
                acc0[dq * 4 + 0] += p0 * vv.x; acc0[dq * 4 + 1] += p0 * vv.y;
                acc0[dq * 4 + 2] += p0 * vv.z; acc0[dq * 4 + 3] += p0 * vv.w;
                acc1[dq * 4 + 0] += p1 * vv.x; acc1[dq * 4 + 1] += p1 * vv.y;
                acc1[dq * 4 + 2] += p1 * vv.z; acc1[dq * 4 + 3] += p1 * vv.w;
            }
        }
    }

    const float r0 = 1.f / l0;
    const float r1 = 1.f / l1;
    float* __restrict__ ob = g_att + (size_t)(b * C_DIM + h * HD) * N_TOK + n0 + t;
#pragma unroll
    for (int d = 0; d < 32; d++) {
        ob[(size_t)d * N_TOK]       = acc0[d] * r0;
        ob[(size_t)d * N_TOK + 128] = acc1[d] * r1;
    }
}

// ===========================================================================
// Launch
// ===========================================================================
extern "C" void kernel_launch(void* const* d_in, const int* in_sizes, int n_in,
                              void* d_out, int out_size)
{
    const float* x       = (const float*)d_in[0];
    const float* w_qkv   = (const float*)d_in[1];
    const float* qkv_g   = (const float*)d_in[2];
    const float* qkv_b   = (const float*)d_in[3];
    const float* qkv_m   = (const float*)d_in[4];
    const float* qkv_v   = (const float*)d_in[5];
    const float* w_pe    = (const float*)d_in[6];
    const float* pe_g    = (const float*)d_in[7];
    const float* pe_b    = (const float*)d_in[8];
    const float* pe_m    = (const float*)d_in[9];
    const float* pe_v    = (const float*)d_in[10];
    const float* w_proj  = (const float*)d_in[11];
    const float* proj_g  = (const float*)d_in[12];
    const float* proj_b  = (const float*)d_in[13];
    const float* proj_m  = (const float*)d_in[14];
    const float* proj_v  = (const float*)d_in[15];
    float* out = (float*)d_out;

    // 1) qkv GEMM + BN -> g_qkv
    {
        dim3 grid(N_TOK / 64, HQKV / 64, BATCH);
        gemm_bn_kernel<0><<<grid, 256>>>(w_qkv, x, nullptr,
                                         qkv_g, qkv_b, qkv_m, qkv_v);
    }
    // 2) depthwise 3x3 PE conv + BN -> g_pe
    {
        dim3 grid(N_TOK / 256, BATCH * C_DIM);
        dwconv_bn_kernel<<<grid, 256>>>(w_pe, pe_g, pe_b, pe_m, pe_v);
    }
    // 3) attention -> g_att
    {
        dim3 grid(N_TOK / 256, BATCH * NH);
        attn_kernel<<<grid, 128>>>();
    }
    // 4) proj GEMM on (g_att + g_pe) + BN -> out
    {
        dim3 grid(N_TOK / 64, C_DIM / 64, BATCH);
        gemm_bn_kernel<1><<<grid, 256>>>(w_proj, nullptr, out,
                                         proj_g, proj_b, proj_m, proj_v);
    }
    (void)in_sizes; (void)n_in; (void)out_size;
}